// round 17
// baseline (speedup 1.0000x reference)
#include <cuda_runtime.h>
#include <cstdint>

// ---------------------------------------------------------------------------
// Playlist model:
//   12 embedding towers (3 single-lookup, 9 mean-pooled over L=100)
//   -> concat [B, 12*512] -> Dense(512) relu -> Dense(256) relu -> Dense(128)
//
// R17 structure (base = R16: mega at its random-gather DRAM floor, 4.95TB/s):
//   * Small tables folded through W1 by linearity -> Y0 [B,512] (g_P 88x512).
//   * ONE persistent fused kernel now runs EVERYTHING after the small-table
//     fold: TMA-ring pooling, GEMM1 (K-chunked split-K tiles), and the whole
//     epilogue (combine1 + GEMM2 + combine2 + GEMM3 + combine3) as gated
//     tickets. R16 lost its mega win to ~78us of serial post-kernels; R17
//     turns that into ~496 tail tickets whose per-mblk chains run in
//     parallel (one ~40us chain depth instead of 78us serial).
//   * Gating: G1 tiles on pool counters; C1(m) on 224 G1 tiles of m; G2 on
//     C1; C2 on G2; G3 on C2; C3 on G3. Every gate targets strictly-earlier
//     tickets; chains root at non-blocking pool items -> deadlock-free.
//   * Fixed-order math everywhere (deterministic).
// ---------------------------------------------------------------------------

#define NB   1024
#define NL   100
#define KBIG 3584          // 7 * 512

__device__ float g_X    [NB * KBIG];
__device__ float g_Y0   [NB * 512];
__device__ float g_P    [88 * 512];
__device__ float g_H1   [NB * 512];
__device__ float g_H2   [NB * 256];
__device__ float g_part [28 * NB * 512];   // gemm1 split-K partials
__device__ float g_part2[ 4 * NB * 256];   // gemm2 split-K partials
__device__ float g_part3[ 2 * NB * 128];   // gemm3 split-K partials

__device__ int g_ticket;
__device__ int g_cnt[7][16];   // pool completion per (feature, mblk)
__device__ int g_dn [5][16];   // 0:G1/m(224) 1:C1/m(8) 2:G2/m(16) 3:C2/m(2) 4:G3/m(4)

// W1 row offsets for the 7 big features in X-column order:
// name, track_can, artist_name, track_uri, track_name, album, genres
__constant__ int c_WOFF[7] = {0, 1024, 1536, 2048, 2560, 3584, 5632};

// ---- queue geometry -------------------------------------------------------
// P stream (per mblk): 4 copy + 160 pool = 164.  G1 stream (per mblk): 224.
// order: P(0..2) pure (492); 13 supergroups [P(m+3):164, G1(m):224] = 388
//        Bresenham; trailing G1(13..15) (672); then per-m epilogue groups
//        [8 C1, 16 G2, 2 C2, 4 G3, 1 C3] = 31 x 16 = 496.
#define N_BASE    (492 + 13 * 388 + 3 * 224)   // 6208
#define N_ITEMS   (N_BASE + 16 * 31)           // 6704

// ---------------------------------------------------------------------------
__device__ __forceinline__ unsigned smem_u32(const void* p) {
    return (unsigned)__cvta_generic_to_shared(p);
}
__device__ __forceinline__ void mbar_init(unsigned mbar, unsigned cnt) {
    asm volatile("mbarrier.init.shared.b64 [%0], %1;" :: "r"(mbar), "r"(cnt) : "memory");
}
__device__ __forceinline__ void mbar_expect_tx(unsigned mbar, unsigned bytes) {
    asm volatile("mbarrier.arrive.expect_tx.shared.b64 _, [%0], %1;"
                 :: "r"(mbar), "r"(bytes) : "memory");
}
__device__ __forceinline__ void mbar_wait(unsigned mbar, int phase) {
    asm volatile(
        "{\n\t.reg .pred P;\n"
        "W%=:\n\t"
        "mbarrier.try_wait.parity.acquire.cta.shared::cta.b64 P, [%0], %1, 0x989680;\n\t"
        "@!P bra W%=;\n\t}"
        :: "r"(mbar), "r"(phase) : "memory");
}
__device__ __forceinline__ void bulk2k(unsigned dst, const void* src, unsigned mb) {
    asm volatile(
        "cp.async.bulk.shared::cluster.global.mbarrier::complete_tx::bytes "
        "[%0], [%1], %2, [%3];"
        :: "r"(dst), "l"(src), "r"(2048), "r"(mb) : "memory");
}

// ---------------------------------------------------------------------------
__global__ void init_mega() {
    if (threadIdx.x == 0) g_ticket = 0;
    if (threadIdx.x < 112) ((int*)g_cnt)[threadIdx.x] = 0;
    if (threadIdx.x < 80)  ((int*)g_dn)[threadIdx.x] = 0;
}

// ---------------------------------------------------------------------------
__global__ void precompute_P(const float* __restrict__ T_collab,
                             const float* __restrict__ T_dur,
                             const float* __restrict__ T_apop,
                             const float* __restrict__ T_afol,
                             const float* __restrict__ T_tpop,
                             const float* __restrict__ W1) {
    __shared__ float s_t[512];
    int r = blockIdx.x;
    const float* T; int row; int off;
    if (r < 4)       { T = T_collab; row = r;      off = 512;  }
    else if (r < 25) { T = T_dur;    row = r - 4;  off = 3072; }
    else if (r < 46) { T = T_apop;   row = r - 25; off = 4096; }
    else if (r < 67) { T = T_afol;   row = r - 46; off = 4608; }
    else             { T = T_tpop;   row = r - 67; off = 5120; }
    int n = threadIdx.x;                       // 512 threads
    s_t[n] = T[row * 512 + n];
    __syncthreads();
    float acc = 0.0f;
    const float* w = W1 + (size_t)off * 512 + n;
    #pragma unroll 8
    for (int k = 0; k < 512; ++k)
        acc = fmaf(s_t[k], w[(size_t)k * 512], acc);
    g_P[r * 512 + n] = acc;
}

// ---------------------------------------------------------------------------
__global__ void small_pool(const int* __restrict__ id_collab,
                           const int* __restrict__ seq_dur,
                           const int* __restrict__ seq_apop,
                           const int* __restrict__ seq_afol,
                           const int* __restrict__ seq_tpop) {
    __shared__ int cnt[21];
    const int b = blockIdx.x, t = threadIdx.x;     // 128 threads, float4 lanes
    const float4* P4 = (const float4*)g_P;

    const int idc = id_collab[b];
    float4 acc = __ldg(&P4[(size_t)idc * 128 + t]);
    float4 ab  = make_float4(0.f, 0.f, 0.f, 0.f);

    const int* seqs[4]  = {seq_dur, seq_apop, seq_afol, seq_tpop};
    const int  pbase[4] = {4, 25, 46, 67};

    for (int j = 0; j < 4; ++j) {
        if (t < 21) cnt[t] = 0;
        __syncthreads();
        if (t < NL) atomicAdd(&cnt[seqs[j][b * NL + t]], 1);
        __syncthreads();
        #pragma unroll
        for (int v = 0; v < 21; ++v) {
            int c = cnt[v];
            if (c) {
                float fc = (float)c;
                float4 p = __ldg(&P4[(size_t)(pbase[j] + v) * 128 + t]);
                ab.x = fmaf(fc, p.x, ab.x);
                ab.y = fmaf(fc, p.y, ab.y);
                ab.z = fmaf(fc, p.z, ab.z);
                ab.w = fmaf(fc, p.w, ab.w);
            }
        }
        __syncthreads();
    }
    float4 o;
    o.x = acc.x + 0.01f * ab.x;
    o.y = acc.y + 0.01f * ab.y;
    o.z = acc.z + 0.01f * ab.z;
    o.w = acc.w + 0.01f * ab.w;
    ((float4*)g_Y0)[(size_t)b * 128 + t] = o;
}

// ---------------------------------------------------------------------------
// generic slab combiner: dst = act(sum_s slab[s] + bias [+ C0]) for rows
// [r0, r0+nrows) x N cols.  Fixed order -> deterministic.
// ---------------------------------------------------------------------------
template<int S, bool RELU, bool ADDC0>
__device__ __forceinline__ void combine_item(
        const float* slabs, int N4, int r0, int nrows,
        const float* bias, const float* C0, float* dst, int tid) {
    const float4* p  = (const float4*)slabs;
    const float4* b4 = (const float4*)bias;
    const float4* c4 = (const float4*)C0;
    float4* d4 = (float4*)dst;
    const int total = nrows * N4;
    const size_t slabstride = (size_t)NB * N4;
    for (int idx = tid; idx < total; idx += 256) {
        int row = r0 + idx / N4;
        int col = idx - (idx / N4) * N4;
        size_t off = (size_t)row * N4 + col;
        float4 v = __ldg(&b4[col]);
        #pragma unroll 7
        for (int s = 0; s < S; ++s) {
            float4 q = p[s * slabstride + off];
            v.x += q.x; v.y += q.y; v.z += q.z; v.w += q.w;
        }
        if (ADDC0) {
            float4 c = c4[off];
            v.x += c.x; v.y += c.y; v.z += c.z; v.w += c.w;
        }
        if (RELU) {
            v.x = fmaxf(v.x, 0.f); v.y = fmaxf(v.y, 0.f);
            v.z = fmaxf(v.z, 0.f); v.w = fmaxf(v.w, 0.f);
        }
        d4[off] = v;
    }
}

// ---------------------------------------------------------------------------
// Fused persistent kernel: pooling + GEMM1 + full MLP epilogue.
// smem layout (floats):
//   [0 .. 10240)      pool rings: half h at h*5120 (2 slots x 5 rows x 512)
//                     gemm overlays [0 .. 2176) (As 16x68 + Bs 16x68)
//   [10240 .. 10496)  staged indices: half h at 10240 + h*128 (ints)
//   [10496 .. 10504)  4 mbarriers (u64): index h*2+s
// ---------------------------------------------------------------------------
struct MegaArgs {
    const float* tbl[7];    // tables in X feature order
    const int*   idx[7];    // f<2: [B] ids; f>=2: [B,L] sequences
    const float* W1; const float* W2; const float* W3;
    const float* b1; const float* b2; const float* b3;
    float* out;
};

__global__ void __launch_bounds__(256) mega(MegaArgs a) {
    __shared__ __align__(1024) float smem[10504];
    __shared__ int s_item;

    const int tid = threadIdx.x;
    float4* X4 = (float4*)g_X;

    // one-time mbarrier init (count=1: the producer's arrive.expect_tx)
    const unsigned mb_base = smem_u32(smem + 10496);
    if (tid == 0) {
        #pragma unroll
        for (int k = 0; k < 4; ++k) mbar_init(mb_base + 8 * k, 1);
    }
    __syncthreads();

    // per-thread phase cursors (10 flips per pool item -> self-restoring)
    int ph0 = 0, ph1 = 0;

    for (;;) {
        if (tid == 0) s_item = atomicAdd(&g_ticket, 1);
        __syncthreads();
        const int it = s_item;
        if (it >= N_ITEMS) break;   // uniform exit

        // ---- decode ------------------------------------------------------
        // kind 0=copy, 1=pool, 2=gemm(any layer), 3=combine(any layer)
        int kind = -1;
        int f = 0, sub = 0, m = 0;
        // gemm fields
        const float *Ag = nullptr, *Bg = nullptr; float* Cg = nullptr;
        int lda = 0, ldn = 0, k0 = 0, n0 = 0;
        bool remap = false;
        int* wptr = nullptr; int wtgt = 0; int* dptr = nullptr;
        // combine fields
        int csel = 0, cr0 = 0;

        if (it < 492) {
            m = it / 164;
            int pi = it - m * 164;
            if (pi < 4) { kind = 0; sub = m * 4 + pi; }
            else { int pp = pi - 4; kind = 1; f = 2 + pp / 32; sub = m * 32 + pp % 32; }
        } else if (it < N_BASE) {
            int t2 = it - 492;
            int sg = t2 / 388;
            int zc, r;
            bool isg = false;
            if (sg < 13) {
                int p = t2 - sg * 388;
                int pa = (p * 164) / 388, pb = ((p + 1) * 164) / 388;
                if (pb > pa) {
                    m = sg + 3;
                    int pi = pa;
                    if (pi < 4) { kind = 0; sub = m * 4 + pi; }
                    else { int pp = pi - 4; kind = 1; f = 2 + pp / 32; sub = m * 32 + pp % 32; }
                } else { m = sg; int gi = p - pa; zc = gi >> 3; r = gi & 7; isg = true; }
            } else {
                int gi = t2 - 13 * 388;
                m = 13 + gi / 224; gi %= 224;
                zc = gi >> 3; r = gi & 7; isg = true;
            }
            if (isg) {
                kind = 2;
                const int z = zc >> 2;
                Ag = g_X; lda = KBIG; Bg = a.W1; ldn = 512;
                Cg = g_part + (size_t)zc * NB * 512;
                k0 = z * 512 + (zc & 3) * 128; n0 = r * 64;
                remap = true;
                wptr = &g_cnt[z][m]; wtgt = (z < 2) ? 4 : 32;
                dptr = &g_dn[0][m];
            }
        } else {
            int t3 = it - N_BASE;
            m = t3 / 31;
            int l = t3 - m * 31;
            if (l < 8) {             // C1: 8 rows each
                kind = 3; csel = 1; cr0 = m * 64 + l * 8;
                wptr = &g_dn[0][m]; wtgt = 224; dptr = &g_dn[1][m];
            } else if (l < 24) {     // G2: 64x64x128 tiles (nblk 4 x kc 4)
                kind = 2;
                int li = l - 8, nblk = li & 3, kc = li >> 2;
                Ag = g_H1; lda = 512; Bg = a.W2; ldn = 256;
                Cg = g_part2 + (size_t)kc * NB * 256;
                k0 = kc * 128; n0 = nblk * 64; remap = false;
                wptr = &g_dn[1][m]; wtgt = 8; dptr = &g_dn[2][m];
            } else if (l < 26) {     // C2: 32 rows each
                kind = 3; csel = 2; cr0 = m * 64 + (l - 24) * 32;
                wptr = &g_dn[2][m]; wtgt = 16; dptr = &g_dn[3][m];
            } else if (l < 30) {     // G3: 64x64x128 tiles (nblk 2 x kc 2)
                kind = 2;
                int li = l - 26, nblk = li & 1, kc = li >> 1;
                Ag = g_H2; lda = 256; Bg = a.W3; ldn = 128;
                Cg = g_part3 + (size_t)kc * NB * 128;
                k0 = kc * 128; n0 = nblk * 64; remap = false;
                wptr = &g_dn[3][m]; wtgt = 2; dptr = &g_dn[4][m];
            } else {                 // C3: 64 rows
                kind = 3; csel = 3; cr0 = m * 64;
                wptr = &g_dn[4][m]; wtgt = 4; dptr = nullptr;
            }
        }

        if (kind == 0) {
            // ---- copy item: 16 b's x 2 single-lookup features ----
            const int b0 = sub * 16;
            const int feat = tid >> 7;           // 0 or 1
            const int col  = tid & 127;
            const float4* T = (const float4*)a.tbl[feat];
            #pragma unroll 4
            for (int k = 0; k < 16; ++k) {
                int b  = b0 + k;
                int id = a.idx[feat][b];
                X4[(size_t)b * 896 + feat * 128 + col] =
                    __ldg(&T[(size_t)id * 128 + col]);
            }
            __threadfence();
            __syncthreads();
            if (tid == 0) {
                atomicAdd(&g_cnt[0][sub >> 2], 1);
                atomicAdd(&g_cnt[1][sub >> 2], 1);
            }
        } else if (kind == 1) {
            // ---- pool item: 2 rows of feature f via TMA bulk ring ----
            const int b0 = sub * 2;
            int* sidx = (int*)(smem + 10240);
            const int* seq = a.idx[f] + b0 * NL;
            for (int i = tid; i < 2 * NL; i += 256)
                sidx[(i / NL) * 128 + (i % NL)] = seq[i];
            __syncthreads();

            const int h = tid >> 7, lt = tid & 127;
            const int* sx = sidx + h * 128;          // 100 indices (bcast LDS)
            const float* Tb = a.tbl[f];
            float* ring = smem + h * 5120;           // 2 slots x 5 rows x 512
            const unsigned ring_u = smem_u32(ring);
            const unsigned mb0 = mb_base + 8 * (h * 2);
            const unsigned mb1 = mb_base + 8 * (h * 2 + 1);
            const bool prod = (lt == 0);

            if (prod) {
                mbar_expect_tx(mb0, 10240);
                #pragma unroll
                for (int q = 0; q < 5; ++q)
                    bulk2k(ring_u + q * 2048u, Tb + (size_t)sx[q] * 512, mb0);
                mbar_expect_tx(mb1, 10240);
                #pragma unroll
                for (int q = 0; q < 5; ++q)
                    bulk2k(ring_u + 10240u + q * 2048u, Tb + (size_t)sx[5 + q] * 512, mb1);
            }

            float4 acc = make_float4(0.f, 0.f, 0.f, 0.f);
            for (int g = 0; g < 20; ++g) {
                const int s = g & 1;
                if (s == 0) { mbar_wait(mb0, ph0); ph0 ^= 1; }
                else        { mbar_wait(mb1, ph1); ph1 ^= 1; }
                const float* buf = ring + s * 2560;
                #pragma unroll
                for (int q = 0; q < 5; ++q) {
                    float4 v = *(const float4*)(buf + q * 512 + lt * 4);
                    acc.x += v.x; acc.y += v.y; acc.z += v.z; acc.w += v.w;
                }
                asm volatile("bar.sync %0, %1;" :: "r"(1 + h), "r"(128) : "memory");
                if (prod && g + 2 < 20) {
                    const unsigned mb = (s == 0) ? mb0 : mb1;
                    mbar_expect_tx(mb, 10240);
                    #pragma unroll
                    for (int q = 0; q < 5; ++q)
                        bulk2k(ring_u + (unsigned)s * 10240u + q * 2048u,
                               Tb + (size_t)sx[(g + 2) * 5 + q] * 512, mb);
                }
            }
            acc.x *= 0.01f; acc.y *= 0.01f; acc.z *= 0.01f; acc.w *= 0.01f;
            X4[(size_t)(b0 + h) * 896 + f * 128 + lt] = acc;

            __threadfence();
            __syncthreads();
            if (tid == 0) atomicAdd(&g_cnt[f][sub >> 5], 1);
        } else if (kind == 2) {
            // ---- generic gemm tile: 64x64x128, split-K partial ----
            if (tid == 0) {
                while (atomicAdd(wptr, 0) < wtgt) __nanosleep(200);
                __threadfence();
            }
            __syncthreads();

            float (*As)[68] = (float(*)[68])smem;
            float (*Bs)[68] = (float(*)[68])(smem + 16 * 68);

            const int tx = tid & 15, ty = tid >> 4;
            const int m0 = m * 64;

            const int a_m = tid >> 2;
            const int a_k = (tid & 3) << 2;
            const int b_k = tid >> 4;
            const int b_n = (tid & 15) << 2;

            float4 ra = *(const float4*)(Ag + (size_t)(m0 + a_m) * lda + k0 + a_k);
            float4 rbv;
            {
                int kg = k0 + b_k;
                int wr = remap ? (c_WOFF[kg >> 9] + (kg & 511)) : kg;
                rbv = *(const float4*)(Bg + (size_t)wr * ldn + n0 + b_n);
            }

            float acc[4][4];
            #pragma unroll
            for (int i = 0; i < 4; ++i)
                #pragma unroll
                for (int j = 0; j < 4; ++j) acc[i][j] = 0.f;

            #pragma unroll 1
            for (int t = 0; t < 8; ++t) {
                As[a_k + 0][a_m] = ra.x;
                As[a_k + 1][a_m] = ra.y;
                As[a_k + 2][a_m] = ra.z;
                As[a_k + 3][a_m] = ra.w;
                *(float4*)&Bs[b_k][b_n] = rbv;
                __syncthreads();

                if (t + 1 < 8) {
                    int kk0 = k0 + (t + 1) * 16;
                    ra = *(const float4*)(Ag + (size_t)(m0 + a_m) * lda + kk0 + a_k);
                    int kg = kk0 + b_k;
                    int wr = remap ? (c_WOFF[kg >> 9] + (kg & 511)) : kg;
                    rbv = *(const float4*)(Bg + (size_t)wr * ldn + n0 + b_n);
                }

                #pragma unroll
                for (int kk = 0; kk < 16; ++kk) {
                    float af[4], bf[4];
                    #pragma unroll
                    for (int i = 0; i < 4; ++i) af[i] = As[kk][ty * 4 + i];
                    #pragma unroll
                    for (int j = 0; j < 4; ++j) bf[j] = Bs[kk][tx * 4 + j];
                    #pragma unroll
                    for (int i = 0; i < 4; ++i)
                        #pragma unroll
                        for (int j = 0; j < 4; ++j)
                            acc[i][j] = fmaf(af[i], bf[j], acc[i][j]);
                }
                __syncthreads();
            }

            #pragma unroll
            for (int i = 0; i < 4; ++i) {
                int row = m0 + ty * 4 + i;
                #pragma unroll
                for (int j = 0; j < 4; ++j)
                    Cg[(size_t)row * ldn + n0 + tx * 4 + j] = acc[i][j];
            }
            __threadfence();
            __syncthreads();
            if (tid == 0) atomicAdd(dptr, 1);
        } else {
            // ---- combine item ----
            if (tid == 0) {
                while (atomicAdd(wptr, 0) < wtgt) __nanosleep(200);
                __threadfence();
            }
            __syncthreads();

            if (csel == 1)
                combine_item<28, true, true >(g_part,  128, cr0,  8, a.b1, g_Y0, g_H1, tid);
            else if (csel == 2)
                combine_item< 4, true, false>(g_part2,  64, cr0, 32, a.b2, nullptr, g_H2, tid);
            else
                combine_item< 2, false,false>(g_part3,  32, cr0, 64, a.b3, nullptr, a.out, tid);

            __threadfence();
            __syncthreads();
            if (tid == 0 && dptr) atomicAdd(dptr, 1);
        }
    }
}

// ---------------------------------------------------------------------------
extern "C" void kernel_launch(void* const* d_in, const int* in_sizes, int n_in,
                              void* d_out, int out_size) {
    (void)in_sizes; (void)n_in; (void)out_size;

    const float* T_name        = (const float*)d_in[0];
    const float* T_collab      = (const float*)d_in[1];
    const float* T_track_can   = (const float*)d_in[2];
    const float* T_artist_name = (const float*)d_in[3];
    const float* T_track_uri   = (const float*)d_in[4];
    const float* T_track_name  = (const float*)d_in[5];
    const float* T_dur         = (const float*)d_in[6];
    const float* T_album       = (const float*)d_in[7];
    const float* T_apop        = (const float*)d_in[8];
    const float* T_afol        = (const float*)d_in[9];
    const float* T_tpop        = (const float*)d_in[10];
    const float* T_genres      = (const float*)d_in[11];
    const float* W1 = (const float*)d_in[12];
    const float* b1 = (const float*)d_in[13];
    const float* W2 = (const float*)d_in[14];
    const float* b2 = (const float*)d_in[15];
    const float* W3 = (const float*)d_in[16];
    const float* b3 = (const float*)d_in[17];
    const int* id_name         = (const int*)d_in[18];
    const int* id_collab       = (const int*)d_in[19];
    const int* id_track_can    = (const int*)d_in[20];
    const int* seq_artist_name = (const int*)d_in[21];
    const int* seq_track_uri   = (const int*)d_in[22];
    const int* seq_track_name  = (const int*)d_in[23];
    const int* seq_dur         = (const int*)d_in[24];
    const int* seq_album       = (const int*)d_in[25];
    const int* seq_apop        = (const int*)d_in[26];
    const int* seq_afol        = (const int*)d_in[27];
    const int* seq_tpop        = (const int*)d_in[28];
    const int* seq_genres      = (const int*)d_in[29];

    MegaArgs ma;
    ma.tbl[0] = T_name;        ma.idx[0] = id_name;
    ma.tbl[1] = T_track_can;   ma.idx[1] = id_track_can;
    ma.tbl[2] = T_artist_name; ma.idx[2] = seq_artist_name;
    ma.tbl[3] = T_track_uri;   ma.idx[3] = seq_track_uri;
    ma.tbl[4] = T_track_name;  ma.idx[4] = seq_track_name;
    ma.tbl[5] = T_album;       ma.idx[5] = seq_album;
    ma.tbl[6] = T_genres;      ma.idx[6] = seq_genres;
    ma.W1 = W1; ma.W2 = W2; ma.W3 = W3;
    ma.b1 = b1; ma.b2 = b2; ma.b3 = b3;
    ma.out = (float*)d_out;

    // small-feature fold (cheap, serial at front; Y0 ready before mega's C1)
    precompute_P<<<88, 512>>>(T_collab, T_dur, T_apop, T_afol, T_tpop, W1);
    small_pool<<<NB, 128>>>(id_collab, seq_dur, seq_apop, seq_afol, seq_tpop);

    // everything else: one persistent fused kernel
    init_mega<<<1, 128>>>();
    mega<<<592, 256>>>(ma);
}